// round 13
// baseline (speedup 1.0000x reference)
#include <cuda_runtime.h>
#include <cuda_fp16.h>

// DWHT (buggy torch in-place semantics) + channel shuffle, fully fused.
// x: (64, 256, 28, 28) f32  ->  out: (64, 512, 28, 28) f32
//
// 8 passes = (F o F)^4; G = F o F maps each aligned 16-channel chunk to a
// fixed signed output set. Channel shuffle (groups=8) folded into affine
// stage-4 addresses.
//
// Round-12 = R11 core (fp16 smem storage / fp32 compute, quad-packed layout,
// zero-pad sparsity, CSE butterfly) + 2-PIXEL-PER-THREAD vectorized global:
//   thread owns pixel pair (2*p2, 2*p2+1): stage-1 loads are LDG.64, stage-4
//   stores are STG.64 -> global LSU instruction count halves per pixel.
//   SMEM = two disjoint 32KB sub-arrays (one per pixel parity); stages 2-3
//   process parities sequentially (R11 register footprint), 6-barrier schedule.

#define NPAIR 32   // pixel pairs per block -> 64 pixels

// ---- butterfly pieces (CSE'd) ----
struct LowOut  { float4 Al; float2 Bl, Dl, Gl; float El; };
struct HighOut { float4 Ah, Ch, G4h; float2 Bh, Dh, G2h, Fh; float Eh; };

__device__ __forceinline__ LowOut lowG(const float w[16]) {
    LowOut o;
    float s[8], t[4], u[4];
#pragma unroll
    for (int i = 0; i < 8; i++) s[i] = w[2*i] + w[2*i+1];
#pragma unroll
    for (int q = 0; q < 4; q++) { t[q] = s[2*q] + s[2*q+1]; u[q] = s[2*q] - s[2*q+1]; }
    o.Al = make_float4(t[0], t[1], t[2], t[3]);
    o.Bl = make_float2(u[0] + u[1], u[2] + u[3]);
    o.Dl = make_float2(t[0] - t[1], t[2] - t[3]);
    o.Gl = make_float2(u[0] - u[1], u[2] - u[3]);
    o.El = o.Bl.x - o.Bl.y;
    return o;
}

__device__ __forceinline__ HighOut highG(const float w[16]) {
    HighOut o;
    float s[8], d[8], t[4], u[4];
#pragma unroll
    for (int i = 0; i < 8; i++) { s[i] = w[2*i] + w[2*i+1]; d[i] = w[2*i] - w[2*i+1]; }
#pragma unroll
    for (int q = 0; q < 4; q++) { t[q] = s[2*q] + s[2*q+1]; u[q] = s[2*q] - s[2*q+1]; }
    o.Ah  = make_float4(t[0], t[1], t[2], t[3]);
    o.Bh  = make_float2(u[0] + u[1], u[2] + u[3]);
    o.Dh  = make_float2(t[0] - t[1], t[2] - t[3]);
    o.G2h = make_float2(u[0] - u[1], u[2] - u[3]);
    o.Eh  = o.Bh.x - o.Bh.y;
    float c0 = d[0]+d[1], c1 = d[2]+d[3], c2 = d[4]+d[5], c3 = d[6]+d[7];
    o.Ch  = make_float4(c0, c1, c2, c3);
    o.G4h = make_float4(d[0]-d[1], d[2]-d[3], d[4]-d[5], d[6]-d[7]);
    o.Fh  = make_float2(c0 - c1, c2 - c3);
    return o;
}

__device__ __forceinline__ void zero16(float w[16]) {
#pragma unroll
    for (int m = 0; m < 16; m++) w[m] = 0.0f;
}

// ---- smem sub-array helpers (R11 quad-packed half layout, index = pair) ----
//   sidx(c,p2) = (c>>2)*128 + 4*p2 + (c&3)   (in halves; 16384 halves = 32KB)
__device__ __forceinline__ void load_chunk(const __half* __restrict__ s, int chunk,
                                           int p2, float w[16]) {
#pragma unroll
    for (int i = 0; i < 4; i++) {
        uint2 raw = *(const uint2*)(s + (4 * chunk + i) * 128 + 4 * p2);
        float2 a = __half22float2(*(__half2*)&raw.x);
        float2 b = __half22float2(*(__half2*)&raw.y);
        w[4*i+0] = a.x; w[4*i+1] = a.y; w[4*i+2] = b.x; w[4*i+3] = b.y;
    }
}
__device__ __forceinline__ void sts4(__half* __restrict__ s, int c, int p2, float4 v) {
    __half2 lo = __floats2half2_rn(v.x, v.y);
    __half2 hi = __floats2half2_rn(v.z, v.w);
    uint2 raw; raw.x = *(unsigned*)&lo; raw.y = *(unsigned*)&hi;
    *(uint2*)(s + (c >> 2) * 128 + 4 * p2) = raw;
}
__device__ __forceinline__ void sts2(__half* __restrict__ s, int c, int p2, float2 v) {
    *(__half2*)(s + (c >> 2) * 128 + 4 * p2 + (c & 3)) = __floats2half2_rn(v.x, v.y);
}
__device__ __forceinline__ void sts1(__half* __restrict__ s, int c, int p2, float v) {
    s[(c >> 2) * 128 + 4 * p2 + (c & 3)] = __float2half_rn(v);
}

__device__ __forceinline__ void store_low(__half* __restrict__ s, int jl, int p2,
                                          const LowOut& o, bool skipAl) {
    if (!skipAl) sts4(s, 4*jl, p2, o.Al);
    sts2(s, 128 + 2*jl, p2, o.Bl);
    sts2(s, 256 + 2*jl, p2, o.Dl);
    sts2(s, 384 + 2*jl, p2, o.Gl);
    sts1(s, 320 + jl, p2, o.El);
}
__device__ __forceinline__ void store_high(__half* __restrict__ s, int jh, int p2,
                                           const HighOut& o, bool skipH4) {
    if (!skipH4) {
        sts4(s, 4*jh,       p2, o.Ah);
        sts4(s, 128 + 4*jh, p2, o.Ch);
        sts4(s, 384 + 4*jh, p2, o.G4h);
    }
    sts2(s, 128 + 2*jh, p2, o.Bh);
    sts2(s, 256 + 2*jh, p2, o.Dh);
    sts2(s, 384 + 2*jh, p2, o.G2h);
    sts2(s, 320 + 2*jh, p2, o.Fh);
    sts1(s, 320 + jh, p2, o.Eh);
}

// One mid-stage parity pass: read chunks (with sparsity), compute, store.
__device__ __forceinline__ void mid_compute(const __half* __restrict__ sin,
                                            int jl, int jh, int p2,
                                            bool rl, bool rh,
                                            LowOut& ol, HighOut& oh) {
    float wl[16], wh[16];
    if (rl) load_chunk(sin, jl, p2, wl); else zero16(wl);
    if (rh) load_chunk(sin, jh, p2, wh); else zero16(wh);
    ol = lowG(wl);   // low-chunk outputs
    oh = highG(wh);  // high-chunk outputs
}

__global__ __launch_bounds__(512, 2)
void dwht_kernel(const float* __restrict__ x, float* __restrict__ out) {
    extern __shared__ __half sm[];      // 2 sub-arrays x 16384 halves = 64 KB
    __half* sub0 = sm;
    __half* sub1 = sm + 16384;

    const int tid = threadIdx.x;
    const int p2  = tid & (NPAIR - 1);  // pixel-pair lane [0,32)
    const int jl  = tid >> 5;           // chunk pair id = warp id [0,16)
    const int jh  = jl + 16;

    const int b    = blockIdx.x / 13;
    const int hw0  = (blockIdx.x % 13) * 64 + 2 * p2;   // even pixel of pair
    const bool valid = (hw0 < 784);                      // pair-level (784 even)
    const float* xp = x   + (size_t)b * (256 * 784) + hw0;
    float*       op = out + (size_t)b * (512 * 784) + hw0;

    float wl0[16], wl1[16];

    // ---- stage 1: vectorized global load (LDG.64 over pixel pair) ----
#pragma unroll
    for (int m = 0; m < 16; m++) {
        float2 v = valid ? *(const float2*)(xp + (16 * jl + m) * 784)
                         : make_float2(0.f, 0.f);
        wl0[m] = v.x; wl1[m] = v.y;
    }
    store_low(sub0, jl, p2, lowG(wl0), false);   // high outputs are exact zeros
    store_low(sub1, jl, p2, lowG(wl1), false);
    __syncthreads();                                        // A

    // ---- stage 2: nonzero input chunks {0,1,2,3,8,9,16,17,20,24,25} ----
    {
        const bool rl = (jl <= 3) | (jl == 8) | (jl == 9);
        const bool rh = (jl <= 1) | (jl == 4) | (jl == 8) | (jl == 9);
        // outputs landing in chunks {1,3,7,15,31} are exact zeros: skip stores
        const bool skipAl = ((jl >= 4) & (jl <= 7)) | (jl >= 12);
        const bool skipH4 = (jl >= 12);
        LowOut ol; HighOut oh;
        mid_compute(sub0, jl, jh, p2, rl, rh, ol, oh);
        __syncthreads();                                    // B: sub0 reads done
        store_low(sub0, jl, p2, ol, skipAl);
        store_high(sub0, jh, p2, oh, skipH4);
        mid_compute(sub1, jl, jh, p2, rl, rh, ol, oh);      // sub1 reads
        __syncthreads();                                    // C
        store_low(sub1, jl, p2, ol, skipAl);
        store_high(sub1, jh, p2, oh, skipH4);
    }

    // ---- stage 3: chunks {1,3,7,15,31} are identically zero: skip reads ----
    {
        const bool rl = !((jl == 1) | (jl == 3) | (jl == 7) | (jl == 15));
        const bool rh = (jl != 15);
        LowOut ol; HighOut oh;
        mid_compute(sub0, jl, jh, p2, rl, rh, ol, oh);
        __syncthreads();                                    // D
        store_low(sub0, jl, p2, ol, false);
        store_high(sub0, jh, p2, oh, false);
        mid_compute(sub1, jl, jh, p2, rl, rh, ol, oh);
        __syncthreads();                                    // E
        store_low(sub1, jl, p2, ol, false);
        store_high(sub1, jh, p2, oh, false);
    }
    __syncthreads();                                        // F

    // ---- stage 4: vectorized shuffled global store (STG.64 per pair) ----
    // Affine shuffle map c=((idx&63)<<3)|(idx>>6):
    //   A:32jl+8q  Ah:+1  Ch:+3  G4h:+7     (base q32)
    //   Bl/Dl/Gl: 16jl+8r+{2,4,6}           (base q16)
    //   Bh/Dh/Fh/G2h: 256+16jl+8r+{2,4,5,6} (base q16h)
    //   El: 8jl+5   Eh: 8jl+133             (base qE)
    if (valid) {
        float* q32  = op + (size_t)(32 * jl) * 784;
        float* q16  = op + (size_t)(16 * jl) * 784;
        float* q16h = q16 + (size_t)256 * 784;
        float* qE   = op + (size_t)(8 * jl) * 784;

        // low families for both parities
        {
            float w0[16], w1[16];
            load_chunk(sub0, jl, p2, w0);
            load_chunk(sub1, jl, p2, w1);
            LowOut a = lowG(w0), c = lowG(w1);
            *(float2*)(q32 + (size_t)( 0*8)*784) = make_float2(a.Al.x, c.Al.x);
            *(float2*)(q32 + (size_t)( 1*8)*784) = make_float2(a.Al.y, c.Al.y);
            *(float2*)(q32 + (size_t)( 2*8)*784) = make_float2(a.Al.z, c.Al.z);
            *(float2*)(q32 + (size_t)( 3*8)*784) = make_float2(a.Al.w, c.Al.w);
            *(float2*)(q16 + (size_t)(0*8+2)*784) = make_float2(a.Bl.x, c.Bl.x);
            *(float2*)(q16 + (size_t)(1*8+2)*784) = make_float2(a.Bl.y, c.Bl.y);
            *(float2*)(q16 + (size_t)(0*8+4)*784) = make_float2(a.Dl.x, c.Dl.x);
            *(float2*)(q16 + (size_t)(1*8+4)*784) = make_float2(a.Dl.y, c.Dl.y);
            *(float2*)(q16 + (size_t)(0*8+6)*784) = make_float2(a.Gl.x, c.Gl.x);
            *(float2*)(q16 + (size_t)(1*8+6)*784) = make_float2(a.Gl.y, c.Gl.y);
            *(float2*)(qE  + (size_t)5*784)       = make_float2(a.El, c.El);
        }
        // high families for both parities
        {
            float w0[16], w1[16];
            load_chunk(sub0, jh, p2, w0);
            load_chunk(sub1, jh, p2, w1);
            HighOut a = highG(w0), c = highG(w1);
            *(float2*)(q32 + (size_t)( 0*8+1)*784) = make_float2(a.Ah.x, c.Ah.x);
            *(float2*)(q32 + (size_t)( 1*8+1)*784) = make_float2(a.Ah.y, c.Ah.y);
            *(float2*)(q32 + (size_t)( 2*8+1)*784) = make_float2(a.Ah.z, c.Ah.z);
            *(float2*)(q32 + (size_t)( 3*8+1)*784) = make_float2(a.Ah.w, c.Ah.w);
            *(float2*)(q32 + (size_t)( 0*8+3)*784) = make_float2(a.Ch.x, c.Ch.x);
            *(float2*)(q32 + (size_t)( 1*8+3)*784) = make_float2(a.Ch.y, c.Ch.y);
            *(float2*)(q32 + (size_t)( 2*8+3)*784) = make_float2(a.Ch.z, c.Ch.z);
            *(float2*)(q32 + (size_t)( 3*8+3)*784) = make_float2(a.Ch.w, c.Ch.w);
            *(float2*)(q32 + (size_t)( 0*8+7)*784) = make_float2(a.G4h.x, c.G4h.x);
            *(float2*)(q32 + (size_t)( 1*8+7)*784) = make_float2(a.G4h.y, c.G4h.y);
            *(float2*)(q32 + (size_t)( 2*8+7)*784) = make_float2(a.G4h.z, c.G4h.z);
            *(float2*)(q32 + (size_t)( 3*8+7)*784) = make_float2(a.G4h.w, c.G4h.w);
            *(float2*)(q16h + (size_t)(0*8+2)*784) = make_float2(a.Bh.x, c.Bh.x);
            *(float2*)(q16h + (size_t)(1*8+2)*784) = make_float2(a.Bh.y, c.Bh.y);
            *(float2*)(q16h + (size_t)(0*8+4)*784) = make_float2(a.Dh.x, c.Dh.x);
            *(float2*)(q16h + (size_t)(1*8+4)*784) = make_float2(a.Dh.y, c.Dh.y);
            *(float2*)(q16h + (size_t)(0*8+5)*784) = make_float2(a.Fh.x, c.Fh.x);
            *(float2*)(q16h + (size_t)(1*8+5)*784) = make_float2(a.Fh.y, c.Fh.y);
            *(float2*)(q16h + (size_t)(0*8+6)*784) = make_float2(a.G2h.x, c.G2h.x);
            *(float2*)(q16h + (size_t)(1*8+6)*784) = make_float2(a.G2h.y, c.G2h.y);
            *(float2*)(qE + (size_t)133*784)       = make_float2(a.Eh, c.Eh);
        }
    }
}

extern "C" void kernel_launch(void* const* d_in, const int* in_sizes, int n_in,
                              void* d_out, int out_size) {
    const float* x = (const float*)d_in[0];
    float* out = (float*)d_out;
    const int smem = 2 * 16384 * sizeof(__half);   // 64 KB
    static bool attr_set = false;                  // idempotent host-side attr
    if (!attr_set) {
        cudaFuncSetAttribute(dwht_kernel,
                             cudaFuncAttributeMaxDynamicSharedMemorySize, smem);
        attr_set = true;
    }
    // 64 images * 13 tiles of 64 pixels (784 = 12*64 + 16; last tile predicated)
    dwht_kernel<<<64 * 13, 512, smem>>>(x, out);
}